// round 13
// baseline (speedup 1.0000x reference)
#include <cuda_runtime.h>
#include <cstdint>
#include <math.h>

// ConvDBN: 2-layer conv RBM + stochastic multinomial pooling.
// Per-output accumulation is a strict sequential fp32 FMA chain in
// k = (kh, kw, c_in) ascending order (bit-matches XLA:CPU Eigen conv).
// f32x2 FMA pairs two independent output-channel chains per lane pair.
// R13: l1 = pre-splatted smem + s-loop row sharing, 2 ch/item (fits 109-reg
//      cap at 600 thr; R12's 4ch variant spilled). l2/w2p = R8 (best known).

#define CP 100  // padded channel stride for L2 smem window

typedef unsigned long long u64;

__device__ float g_h1[64 * 30 * 30 * 96];     // h1 NHWC: [b][h][w][c]
__device__ float g_w2p8[49 * 24 * 96 * 8];    // W2: [kk][octet][c][8ch] (pairs interleaved)

// ---------------- f32x2 helpers ----------------
__device__ __forceinline__ void ffma2(u64 &d, u64 a, u64 b) {
  asm("fma.rn.f32x2 %0, %1, %2, %0;" : "+l"(d) : "l"(a), "l"(b));
}
__device__ __forceinline__ u64 splat2(float v) {
  u64 r;
  asm("mov.b64 %0, {%1, %1};" : "=l"(r) : "r"(__float_as_uint(v)));
  return r;
}
__device__ __forceinline__ float lane0(u64 a) { return __uint_as_float((uint32_t)a); }
__device__ __forceinline__ float lane1(u64 a) { return __uint_as_float((uint32_t)(a >> 32)); }

// ---------------- Threefry-2x32 (JAX partitionable) ----------------
__host__ __device__ __forceinline__ void tf2x32(uint32_t k0, uint32_t k1,
                                                uint32_t x0, uint32_t x1,
                                                uint32_t &o0, uint32_t &o1) {
  uint32_t ks2 = k0 ^ k1 ^ 0x1BD11BDAu;
  x0 += k0; x1 += k1;
#define TF_RND(r) { x0 += x1; x1 = (x1 << (r)) | (x1 >> (32 - (r))); x1 ^= x0; }
  TF_RND(13) TF_RND(15) TF_RND(26) TF_RND(6)
  x0 += k1;  x1 += ks2 + 1u;
  TF_RND(17) TF_RND(29) TF_RND(16) TF_RND(24)
  x0 += ks2; x1 += k0 + 2u;
  TF_RND(13) TF_RND(15) TF_RND(26) TF_RND(6)
  x0 += k0;  x1 += k1 + 3u;
  TF_RND(17) TF_RND(29) TF_RND(16) TF_RND(24)
  x0 += k1;  x1 += ks2 + 4u;
  TF_RND(13) TF_RND(15) TF_RND(26) TF_RND(6)
  x0 += ks2; x1 += k0 + 5u;
#undef TF_RND
  o0 = x0; o1 = x1;
}

__device__ __forceinline__ float gumbel_at(uint32_t k0, uint32_t k1, uint32_t idx) {
  uint32_t o0, o1;
  tf2x32(k0, k1, 0u, idx, o0, o1);
  uint32_t bits = o0 ^ o1;
  float f = __uint_as_float((bits >> 9) | 0x3F800000u) - 1.0f;
  const float tiny = 1.1754943508222875e-38f;
  f = fmaxf(tiny, f + tiny);
  return -logf(-logf(f));
}

__device__ __forceinline__ float pool9(const float p[9], uint32_t k0, uint32_t k1,
                                       uint32_t base) {
  float best = -1e30f;
  int win = 0;
#pragma unroll
  for (int j = 0; j < 9; j++) {
    float m = logf(p[j] + 1e-8f) + gumbel_at(k0, k1, base + (uint32_t)j);
    if (m > best) { best = m; win = j; }
  }
  return p[win];
}

// ---------------- W2 prep: [c2][c][kh][kw] -> [kk][o][c][t] ----------------
__global__ void w2p_kernel(const float *__restrict__ w2) {
  int idx = blockIdx.x * 256 + threadIdx.x;   // 49*24*96*8 = 903168 exact
  int t = idx & 7;
  int r = idx >> 3;
  int c = r % 96;
  int u = r / 96;
  int o = u % 24;
  int kk = u / 24;
  g_w2p8[idx] = w2[((o * 8 + t) * 96 + c) * 49 + kk];
}

// ---------------- Layer 1: s-loop, pre-splatted x, 2 ch/item ----------------
// grid (64, 6, 3): (batch, 16-ch group, row decade). 600 threads, 4 items each.
// xs2: [3][36][96] u64 (pre-splatted (v,v)); ws2: [8 pairs][147 taps] u64.
__global__ void __launch_bounds__(600) l1_kernel(const float *__restrict__ x,
                                                 const float *__restrict__ w1,
                                                 const float *__restrict__ b1,
                                                 uint32_t k0, uint32_t k1) {
  extern __shared__ u64 sm64[];
  u64 *xs2 = sm64;                     // 10368 u64
  u64 *ws2 = sm64 + 10368;             // 8*147 u64
  const int b = blockIdx.x, cg = blockIdx.y, d = blockIdx.z;
  const int cbase = cg * 16;

  // Stage pre-splatted activations (rows 30d .. 30d+35, all 3 channels).
  for (int i = threadIdx.x; i < 2592; i += 600) {
    int e = i * 4;
    int ci = e / 3456;                 // 36*96
    int r = e - ci * 3456;
    float4 dv = *(const float4 *)(x + (size_t)b * 27648 + ci * 9216 + (30 * d) * 96 + r);
    u64 *dst = xs2 + e;
    uint32_t bx = __float_as_uint(dv.x); dst[0] = (u64)bx | ((u64)bx << 32);
    uint32_t by = __float_as_uint(dv.y); dst[1] = (u64)by | ((u64)by << 32);
    uint32_t bz = __float_as_uint(dv.z); dst[2] = (u64)bz | ((u64)bz << 32);
    uint32_t bw = __float_as_uint(dv.w); dst[3] = (u64)bw | ((u64)bw << 32);
  }
  // ws2[pr*147 + m] = pack(w1[ch 2pr], w1[ch 2pr+1]) at tap m.
  for (int i = threadIdx.x; i < 8 * 147; i += 600) {
    int pr = i / 147, m = i - pr * 147;
    float a = w1[(cbase + pr * 2 + 0) * 147 + m];
    float bb = w1[(cbase + pr * 2 + 1) * 147 + m];
    ws2[i] = (u64)__float_as_uint(a) | ((u64)__float_as_uint(bb) << 32);
  }
  __syncthreads();

  for (int item = threadIdx.x; item < 2400; item += 600) {
    const int pr = item / 300, pos = item - pr * 300;   // pr: channel pair 0..7
    const int hl = pos / 30, wb = pos - hl * 30;
    const int r0 = hl * 3, q0 = wb * 3;
    const u64 *wp = ws2 + pr * 147;

    u64 acc[9];
#pragma unroll
    for (int j = 0; j < 9; j++) acc[j] = 0ull;

    // s = dy + kh: each input row loaded once, shared across dy's using it.
    // Per-acc (dy,dx) order: s asc => kh asc; then kw; then ci (innermost). Bit-exact.
#pragma unroll
    for (int s = 0; s < 9; s++) {
      u64 v[3][9];
#pragma unroll
      for (int ci = 0; ci < 3; ci++) {
        const u64 *row = xs2 + (ci * 36 + r0 + s) * 96 + q0;
#pragma unroll
        for (int e = 0; e < 9; e++) v[ci][e] = row[e];
      }
      const int dy_lo = (s > 6) ? (s - 6) : 0;
      const int dy_hi = (s < 2) ? s : 2;
#pragma unroll
      for (int dy = 0; dy < 3; dy++) {
        if (dy < dy_lo || dy > dy_hi) continue;   // compile-time dead code
        const int kh = s - dy;
#pragma unroll
        for (int kw = 0; kw < 7; kw++) {
#pragma unroll
          for (int ci = 0; ci < 3; ci++) {
            const u64 wA = wp[ci * 49 + kh * 7 + kw];   // warp-uniform LDS.64
#pragma unroll
            for (int dx = 0; dx < 3; dx++)
              ffma2(acc[dy * 3 + dx], v[ci][kw + dx], wA);
          }
        }
      }
    }

    const int hb = d * 10 + hl;
    const int posg = hb * 30 + wb;
#pragma unroll
    for (int s2 = 0; s2 < 2; s2++) {
      const int c = cbase + pr * 2 + s2;
      float accs[9];
#pragma unroll
      for (int j = 0; j < 9; j++)
        accs[j] = s2 ? lane1(acc[j]) : lane0(acc[j]);
      const float bias = b1[c];
      float p[9];
#pragma unroll
      for (int j = 0; j < 9; j++) {
        float pre = (accs[j] + bias) / 0.04f;
        p[j] = 1.0f / (1.0f + expf(-pre));
      }
      const uint32_t base = (((uint32_t)(b * 96 + c)) * 900u + (uint32_t)posg) * 9u;
      g_h1[((b * 30 + hb) * 30 + wb) * 96 + c] = pool9(p, k0, k1, base);
    }
  }
}

// ---------------- Layer 2: 8 ch/thread, pipelined weights (R8, best) ----------------
// grid (64, 8, 2): (batch, pooled row, wb-half). 96 threads = 24 octets x 4 wl.
__global__ void __launch_bounds__(96, 3) l2_kernel(const float *__restrict__ b2,
                                                   float *__restrict__ out,
                                                   uint32_t k0, uint32_t k1) {
  extern __shared__ float hs[];  // [9 rows][18 cols][CP]
  const int b = blockIdx.x, hb = blockIdx.y, sHalf = blockIdx.z;
  const int tid = threadIdx.x;

  for (int i = tid; i < 9 * 432; i += 96) {
    int row = i / 432, r = i - row * 432;
    int e = r * 4;
    int cl = e / 96, c = e - cl * 96;
    float4 dv = *(const float4 *)(g_h1 +
        ((size_t)(b * 30 + hb * 3 + row) * 30 + 12 * sHalf) * 96 + e);
    *(float4 *)&hs[(row * 18 + cl) * CP + c] = dv;
  }
  __syncthreads();

  const int o = tid >> 2;
  const int wl = tid & 3;
  const int wb = sHalf * 4 + wl;
  const int q0 = wl * 3;

  u64 acc[4][9];
#pragma unroll
  for (int i = 0; i < 4; i++)
#pragma unroll
    for (int j = 0; j < 9; j++) acc[i][j] = 0ull;

  const u64 *w8 = (const u64 *)g_w2p8;

  const u64 *wk = w8 + (size_t)o * 384;   // kk = 0
  ulonglong2 P[8];
  {
    const ulonglong2 *p0 = (const ulonglong2 *)wk;
#pragma unroll
    for (int t = 0; t < 8; t++) P[t] = p0[t];
  }

#pragma unroll 1
  for (int kh = 0; kh < 7; kh++) {
#pragma unroll 1
    for (int kw = 0; kw < 7; kw++) {
      const int kk = kh * 7 + kw;
      const float *hrow = hs + (kh * 18 + q0 + kw) * CP;
      const u64 *wk_next =
          w8 + ((size_t)((kk < 48) ? kk + 1 : kk) * 24 + o) * 384;
#pragma unroll 2
      for (int c4 = 0; c4 < 24; c4++) {
        ulonglong2 W[8];
#pragma unroll
        for (int t = 0; t < 8; t++) W[t] = P[t];
        const ulonglong2 *np = (const ulonglong2 *)(
            (c4 < 23) ? (wk + (c4 + 1) * 16) : wk_next);
#pragma unroll
        for (int t = 0; t < 8; t++) P[t] = np[t];

        // Per-acc chain order over (kh, kw, c4, cc) = (kh, kw, c) ascending.
#pragma unroll
        for (int j = 0; j < 9; j++) {
          const int dy = j / 3, dx = j - dy * 3;
          const float4 vv = *(const float4 *)(hrow + (dy * 18 + dx) * CP + c4 * 4);
#pragma unroll
          for (int cc = 0; cc < 4; cc++) {
            const u64 vs = splat2(((const float *)&vv)[cc]);
            ffma2(acc[0][j], vs, W[cc * 2].x);
            ffma2(acc[1][j], vs, W[cc * 2].y);
            ffma2(acc[2][j], vs, W[cc * 2 + 1].x);
            ffma2(acc[3][j], vs, W[cc * 2 + 1].y);
          }
        }
      }
      wk = wk_next;
    }
  }

#pragma unroll
  for (int i = 0; i < 4; i++) {
#pragma unroll
    for (int s = 0; s < 2; s++) {
      const int c2 = o * 8 + i * 2 + s;
      float accs[9];
#pragma unroll
      for (int j = 0; j < 9; j++)
        accs[j] = s ? lane1(acc[i][j]) : lane0(acc[i][j]);
      const float bias = b2[c2];
      float p[9];
#pragma unroll
      for (int j = 0; j < 9; j++) {
        float pre = (accs[j] + bias) / 0.04f;
        p[j] = 1.0f / (1.0f + expf(-pre));
      }
      const uint32_t oidx =
          (((uint32_t)b * 192u + (uint32_t)c2) * 8u + (uint32_t)hb) * 8u + (uint32_t)wb;
      out[oidx] = pool9(p, k0, k1, oidx * 9u);
    }
  }
}

// ---------------- Launch ----------------
extern "C" void kernel_launch(void *const *d_in, const int *in_sizes, int n_in,
                              void *d_out, int out_size) {
  const float *x  = (const float *)d_in[0];
  const float *w1 = (const float *)d_in[1];
  const float *b1 = (const float *)d_in[2];
  const float *w2 = (const float *)d_in[3];
  const float *b2 = (const float *)d_in[4];

  uint32_t kp1_0, kp1_1, kp2_0, kp2_1;
  tf2x32(0u, 42u, 0u, 0u, kp1_0, kp1_1);
  tf2x32(0u, 42u, 0u, 1u, kp2_0, kp2_1);

  const int l1_smem = (10368 + 8 * 147) * 8;     // 92,352 B
  const int l2_smem = 9 * 18 * CP * 4;           // 64,800 B
  cudaFuncSetAttribute(l1_kernel, cudaFuncAttributeMaxDynamicSharedMemorySize, l1_smem);
  cudaFuncSetAttribute(l2_kernel, cudaFuncAttributeMaxDynamicSharedMemorySize, l2_smem);

  l1_kernel<<<dim3(64, 6, 3), 600, l1_smem>>>(x, w1, b1, kp1_0, kp1_1);
  w2p_kernel<<<49 * 24 * 96 * 8 / 256, 256>>>(w2);
  l2_kernel<<<dim3(64, 8, 2), 96, l2_smem>>>(b2, (float *)d_out, kp2_0, kp2_1);
}

// round 15
// speedup vs baseline: 3.2685x; 3.2685x over previous
#include <cuda_runtime.h>
#include <cstdint>
#include <math.h>

// ConvDBN: 2-layer conv RBM + stochastic multinomial pooling.
// Per-output accumulation is a strict sequential fp32 FMA chain in
// k = (kh, kw, c_in) ascending order (bit-matches XLA:CPU Eigen conv).
// f32x2 FMA pairs two independent output-channel chains per lane pair.
// R15: l1 = R11 body (dy-split, rolled kh, float window) retiled to 5-row
//      decades / 300 thr / 2 blocks/SM. l2/w2p = R8 (best known).

#define CP 100  // padded channel stride for L2 smem window

typedef unsigned long long u64;

__device__ float g_h1[64 * 30 * 30 * 96];     // h1 NHWC: [b][h][w][c]
__device__ float g_w2p8[49 * 24 * 96 * 8];    // W2: [kk][octet][c][8ch] (pairs interleaved)

// ---------------- f32x2 helpers ----------------
__device__ __forceinline__ void ffma2(u64 &d, u64 a, u64 b) {
  asm("fma.rn.f32x2 %0, %1, %2, %0;" : "+l"(d) : "l"(a), "l"(b));
}
__device__ __forceinline__ u64 splat2(float v) {
  u64 r;
  asm("mov.b64 %0, {%1, %1};" : "=l"(r) : "r"(__float_as_uint(v)));
  return r;
}
__device__ __forceinline__ float lane0(u64 a) { return __uint_as_float((uint32_t)a); }
__device__ __forceinline__ float lane1(u64 a) { return __uint_as_float((uint32_t)(a >> 32)); }

// ---------------- Threefry-2x32 (JAX partitionable) ----------------
__host__ __device__ __forceinline__ void tf2x32(uint32_t k0, uint32_t k1,
                                                uint32_t x0, uint32_t x1,
                                                uint32_t &o0, uint32_t &o1) {
  uint32_t ks2 = k0 ^ k1 ^ 0x1BD11BDAu;
  x0 += k0; x1 += k1;
#define TF_RND(r) { x0 += x1; x1 = (x1 << (r)) | (x1 >> (32 - (r))); x1 ^= x0; }
  TF_RND(13) TF_RND(15) TF_RND(26) TF_RND(6)
  x0 += k1;  x1 += ks2 + 1u;
  TF_RND(17) TF_RND(29) TF_RND(16) TF_RND(24)
  x0 += ks2; x1 += k0 + 2u;
  TF_RND(13) TF_RND(15) TF_RND(26) TF_RND(6)
  x0 += k0;  x1 += k1 + 3u;
  TF_RND(17) TF_RND(29) TF_RND(16) TF_RND(24)
  x0 += k1;  x1 += ks2 + 4u;
  TF_RND(13) TF_RND(15) TF_RND(26) TF_RND(6)
  x0 += ks2; x1 += k0 + 5u;
#undef TF_RND
  o0 = x0; o1 = x1;
}

__device__ __forceinline__ float gumbel_at(uint32_t k0, uint32_t k1, uint32_t idx) {
  uint32_t o0, o1;
  tf2x32(k0, k1, 0u, idx, o0, o1);
  uint32_t bits = o0 ^ o1;
  float f = __uint_as_float((bits >> 9) | 0x3F800000u) - 1.0f;
  const float tiny = 1.1754943508222875e-38f;
  f = fmaxf(tiny, f + tiny);
  return -logf(-logf(f));
}

__device__ __forceinline__ float pool9(const float p[9], uint32_t k0, uint32_t k1,
                                       uint32_t base) {
  float best = -1e30f;
  int win = 0;
#pragma unroll
  for (int j = 0; j < 9; j++) {
    float m = logf(p[j] + 1e-8f) + gumbel_at(k0, k1, base + (uint32_t)j);
    if (m > best) { best = m; win = j; }
  }
  return p[win];
}

// ---------------- W2 prep: [c2][c][kh][kw] -> [kk][o][c][t] ----------------
__global__ void w2p_kernel(const float *__restrict__ w2) {
  int idx = blockIdx.x * 256 + threadIdx.x;   // 49*24*96*8 = 903168 exact
  int t = idx & 7;
  int r = idx >> 3;
  int c = r % 96;
  int u = r / 96;
  int o = u % 24;
  int kk = u / 24;
  g_w2p8[idx] = w2[((o * 8 + t) * 96 + c) * 49 + kk];
}

// ---------------- Layer 1: dy-split, 4 ch/item, 5-row decades ----------------
// grid (64, 6, 6): (batch, 16-ch group, 5-row decade). 300 threads, 2 blocks/SM.
// Items: 4 channel-quads x 150 positions = 600; exactly 2 per thread.
// Body identical to R11 (rolled kh loop, float v[3][9] window).
__global__ void __launch_bounds__(300, 2) l1_kernel(const float *__restrict__ x,
                                                    const float *__restrict__ w1,
                                                    const float *__restrict__ b1,
                                                    uint32_t k0, uint32_t k1) {
  extern __shared__ float sm[];
  float *xs = sm;                        // [3][21][96] = 6048 floats
  u64 *ws4 = (u64 *)(sm + 6048);         // [4 quads][147 taps][2 pairs]
  const int b = blockIdx.x, cg = blockIdx.y, d = blockIdx.z;
  const int cbase = cg * 16;

  // Stage 21 input rows (15d .. 15d+20) for all 3 channels.
  for (int i = threadIdx.x; i < 1512; i += 300) {   // 6048/4 float4
    int e = i * 4;
    int ci = e / 2016;                 // 21*96
    int r = e - ci * 2016;
    ((float4 *)xs)[i] =
        *(const float4 *)(x + (size_t)b * 27648 + ci * 9216 + (15 * d) * 96 + r);
  }
  // ws4[(qo*147 + tap)*2 + s] = pack(w1[ch 4qo+2s], w1[ch 4qo+2s+1]).
  for (int i = threadIdx.x; i < 8 * 147; i += 300) {
    int pr = i / 147, m = i - pr * 147;   // pr = 2*qo + s
    int qo = pr >> 1, s = pr & 1;
    float a = w1[(cbase + qo * 4 + s * 2 + 0) * 147 + m];
    float bb = w1[(cbase + qo * 4 + s * 2 + 1) * 147 + m];
    ws4[(qo * 147 + m) * 2 + s] =
        (u64)__float_as_uint(a) | ((u64)__float_as_uint(bb) << 32);
  }
  __syncthreads();

  for (int item = threadIdx.x; item < 600; item += 300) {
    const int qo = item / 150, pos = item - qo * 150;
    const int hl = pos / 30, wb = pos - hl * 30;   // hl: local pooled row 0..4
    const int r0 = hl * 3, q0 = wb * 3;
    const u64 *wq = ws4 + qo * 294;

    u64 acc0[9], acc1[9];
#pragma unroll
    for (int j = 0; j < 9; j++) { acc0[j] = 0ull; acc1[j] = 0ull; }

#pragma unroll
    for (int dy = 0; dy < 3; dy++) {
#pragma unroll 1
      for (int kh = 0; kh < 7; kh++) {
        // 27-float window: input row (r0+dy+kh) per ci, cols q0..q0+8.
        float v[3][9];
#pragma unroll
        for (int ci = 0; ci < 3; ci++) {
          const float *row = xs + (ci * 21 + r0 + dy + kh) * 96 + q0;
#pragma unroll
          for (int e = 0; e < 9; e++) v[ci][e] = row[e];
        }
        const u64 *wkh = wq + kh * 14;
#pragma unroll
        for (int kw = 0; kw < 7; kw++) {
#pragma unroll
          for (int ci = 0; ci < 3; ci++) {
            const ulonglong2 wv =
                *(const ulonglong2 *)(wkh + (ci * 49 + kw) * 2);
#pragma unroll
            for (int dx = 0; dx < 3; dx++) {
              const u64 vs = splat2(v[ci][kw + dx]);
              ffma2(acc0[dy * 3 + dx], vs, wv.x);
              ffma2(acc1[dy * 3 + dx], vs, wv.y);
            }
          }
        }
      }
    }

    const int hb = d * 5 + hl;
    const int posg = hb * 30 + wb;
#pragma unroll
    for (int k4 = 0; k4 < 4; k4++) {
      const int c = cbase + qo * 4 + k4;
      float accs[9];
#pragma unroll
      for (int j = 0; j < 9; j++) {
        u64 a = (k4 < 2) ? acc0[j] : acc1[j];
        accs[j] = (k4 & 1) ? lane1(a) : lane0(a);
      }
      const float bias = b1[c];
      float p[9];
#pragma unroll
      for (int j = 0; j < 9; j++) {
        float pre = (accs[j] + bias) / 0.04f;
        p[j] = 1.0f / (1.0f + expf(-pre));
      }
      const uint32_t base = (((uint32_t)(b * 96 + c)) * 900u + (uint32_t)posg) * 9u;
      g_h1[((b * 30 + hb) * 30 + wb) * 96 + c] = pool9(p, k0, k1, base);
    }
  }
}

// ---------------- Layer 2: 8 ch/thread, pipelined weights (R8, best) ----------------
// grid (64, 8, 2): (batch, pooled row, wb-half). 96 threads = 24 octets x 4 wl.
__global__ void __launch_bounds__(96, 3) l2_kernel(const float *__restrict__ b2,
                                                   float *__restrict__ out,
                                                   uint32_t k0, uint32_t k1) {
  extern __shared__ float hs[];  // [9 rows][18 cols][CP]
  const int b = blockIdx.x, hb = blockIdx.y, sHalf = blockIdx.z;
  const int tid = threadIdx.x;

  for (int i = tid; i < 9 * 432; i += 96) {
    int row = i / 432, r = i - row * 432;
    int e = r * 4;
    int cl = e / 96, c = e - cl * 96;
    float4 dv = *(const float4 *)(g_h1 +
        ((size_t)(b * 30 + hb * 3 + row) * 30 + 12 * sHalf) * 96 + e);
    *(float4 *)&hs[(row * 18 + cl) * CP + c] = dv;
  }
  __syncthreads();

  const int o = tid >> 2;
  const int wl = tid & 3;
  const int wb = sHalf * 4 + wl;
  const int q0 = wl * 3;

  u64 acc[4][9];
#pragma unroll
  for (int i = 0; i < 4; i++)
#pragma unroll
    for (int j = 0; j < 9; j++) acc[i][j] = 0ull;

  const u64 *w8 = (const u64 *)g_w2p8;

  const u64 *wk = w8 + (size_t)o * 384;   // kk = 0
  ulonglong2 P[8];
  {
    const ulonglong2 *p0 = (const ulonglong2 *)wk;
#pragma unroll
    for (int t = 0; t < 8; t++) P[t] = p0[t];
  }

#pragma unroll 1
  for (int kh = 0; kh < 7; kh++) {
#pragma unroll 1
    for (int kw = 0; kw < 7; kw++) {
      const int kk = kh * 7 + kw;
      const float *hrow = hs + (kh * 18 + q0 + kw) * CP;
      const u64 *wk_next =
          w8 + ((size_t)((kk < 48) ? kk + 1 : kk) * 24 + o) * 384;
#pragma unroll 2
      for (int c4 = 0; c4 < 24; c4++) {
        ulonglong2 W[8];
#pragma unroll
        for (int t = 0; t < 8; t++) W[t] = P[t];
        const ulonglong2 *np = (const ulonglong2 *)(
            (c4 < 23) ? (wk + (c4 + 1) * 16) : wk_next);
#pragma unroll
        for (int t = 0; t < 8; t++) P[t] = np[t];

        // Per-acc chain order over (kh, kw, c4, cc) = (kh, kw, c) ascending.
#pragma unroll
        for (int j = 0; j < 9; j++) {
          const int dy = j / 3, dx = j - dy * 3;
          const float4 vv = *(const float4 *)(hrow + (dy * 18 + dx) * CP + c4 * 4);
#pragma unroll
          for (int cc = 0; cc < 4; cc++) {
            const u64 vs = splat2(((const float *)&vv)[cc]);
            ffma2(acc[0][j], vs, W[cc * 2].x);
            ffma2(acc[1][j], vs, W[cc * 2].y);
            ffma2(acc[2][j], vs, W[cc * 2 + 1].x);
            ffma2(acc[3][j], vs, W[cc * 2 + 1].y);
          }
        }
      }
      wk = wk_next;
    }
  }

#pragma unroll
  for (int i = 0; i < 4; i++) {
#pragma unroll
    for (int s = 0; s < 2; s++) {
      const int c2 = o * 8 + i * 2 + s;
      float accs[9];
#pragma unroll
      for (int j = 0; j < 9; j++)
        accs[j] = s ? lane1(acc[i][j]) : lane0(acc[i][j]);
      const float bias = b2[c2];
      float p[9];
#pragma unroll
      for (int j = 0; j < 9; j++) {
        float pre = (accs[j] + bias) / 0.04f;
        p[j] = 1.0f / (1.0f + expf(-pre));
      }
      const uint32_t oidx =
          (((uint32_t)b * 192u + (uint32_t)c2) * 8u + (uint32_t)hb) * 8u + (uint32_t)wb;
      out[oidx] = pool9(p, k0, k1, oidx * 9u);
    }
  }
}

// ---------------- Launch ----------------
extern "C" void kernel_launch(void *const *d_in, const int *in_sizes, int n_in,
                              void *d_out, int out_size) {
  const float *x  = (const float *)d_in[0];
  const float *w1 = (const float *)d_in[1];
  const float *b1 = (const float *)d_in[2];
  const float *w2 = (const float *)d_in[3];
  const float *b2 = (const float *)d_in[4];

  uint32_t kp1_0, kp1_1, kp2_0, kp2_1;
  tf2x32(0u, 42u, 0u, 0u, kp1_0, kp1_1);
  tf2x32(0u, 42u, 0u, 1u, kp2_0, kp2_1);

  const int l1_smem = 6048 * 4 + 8 * 147 * 8;    // 33,600 B
  const int l2_smem = 9 * 18 * CP * 4;           // 64,800 B
  cudaFuncSetAttribute(l1_kernel, cudaFuncAttributeMaxDynamicSharedMemorySize, l1_smem);
  cudaFuncSetAttribute(l2_kernel, cudaFuncAttributeMaxDynamicSharedMemorySize, l2_smem);

  l1_kernel<<<dim3(64, 6, 6), 300, l1_smem>>>(x, w1, b1, kp1_0, kp1_1);
  w2p_kernel<<<49 * 24 * 96 * 8 / 256, 256>>>(w2);
  l2_kernel<<<dim3(64, 8, 2), 96, l2_smem>>>(b2, (float *)d_out, kp2_0, kp2_1);
}

// round 17
// speedup vs baseline: 3.4674x; 1.0609x over previous
#include <cuda_runtime.h>
#include <cstdint>
#include <math.h>

// ConvDBN: 2-layer conv RBM + stochastic multinomial pooling.
// Per-output accumulation is a strict sequential fp32 FMA chain in
// k = (kh, kw, c_in) ascending order (bit-matches XLA:CPU Eigen conv).
// f32x2 FMA pairs two independent output-channel chains per lane pair.
// R17: l1 = R11, l2/w2p = R8 (proven 2231us combo); pool argmax via the
//      EXACT monotone transform exp(metric) = (p+eps)/(-log u): one exact
//      logf per element (precision-critical inner log kept IEEE), winner
//      compared by cross-multiplication. No fast-math on the RNG path.

#define CP 100  // padded channel stride for L2 smem window

typedef unsigned long long u64;

__device__ float g_h1[64 * 30 * 30 * 96];     // h1 NHWC: [b][h][w][c]
__device__ float g_w2p8[49 * 24 * 96 * 8];    // W2: [kk][octet][c][8ch] (pairs interleaved)

// ---------------- f32x2 helpers ----------------
__device__ __forceinline__ void ffma2(u64 &d, u64 a, u64 b) {
  asm("fma.rn.f32x2 %0, %1, %2, %0;" : "+l"(d) : "l"(a), "l"(b));
}
__device__ __forceinline__ u64 splat2(float v) {
  u64 r;
  asm("mov.b64 %0, {%1, %1};" : "=l"(r) : "r"(__float_as_uint(v)));
  return r;
}
__device__ __forceinline__ float lane0(u64 a) { return __uint_as_float((uint32_t)a); }
__device__ __forceinline__ float lane1(u64 a) { return __uint_as_float((uint32_t)(a >> 32)); }

// ---------------- Threefry-2x32 (JAX partitionable) ----------------
__host__ __device__ __forceinline__ void tf2x32(uint32_t k0, uint32_t k1,
                                                uint32_t x0, uint32_t x1,
                                                uint32_t &o0, uint32_t &o1) {
  uint32_t ks2 = k0 ^ k1 ^ 0x1BD11BDAu;
  x0 += k0; x1 += k1;
#define TF_RND(r) { x0 += x1; x1 = (x1 << (r)) | (x1 >> (32 - (r))); x1 ^= x0; }
  TF_RND(13) TF_RND(15) TF_RND(26) TF_RND(6)
  x0 += k1;  x1 += ks2 + 1u;
  TF_RND(17) TF_RND(29) TF_RND(16) TF_RND(24)
  x0 += ks2; x1 += k0 + 2u;
  TF_RND(13) TF_RND(15) TF_RND(26) TF_RND(6)
  x0 += k0;  x1 += k1 + 3u;
  TF_RND(17) TF_RND(29) TF_RND(16) TF_RND(24)
  x0 += k1;  x1 += ks2 + 4u;
  TF_RND(13) TF_RND(15) TF_RND(26) TF_RND(6)
  x0 += ks2; x1 += k0 + 5u;
#undef TF_RND
  o0 = x0; o1 = x1;
}

// t = -log(u) for the pool element (exact libm logf; precision-critical).
__device__ __forceinline__ float neglogu_at(uint32_t k0, uint32_t k1, uint32_t idx) {
  uint32_t o0, o1;
  tf2x32(k0, k1, 0u, idx, o0, o1);
  uint32_t bits = o0 ^ o1;
  float f = __uint_as_float((bits >> 9) | 0x3F800000u) - 1.0f;
  const float tiny = 1.1754943508222875e-38f;
  f = fmaxf(tiny, f + tiny);                     // u in [tiny, 1)
  return -logf(f);                               // t in [~1.19e-7, ~87.3]
}

// winner = argmax_j (p_j+1e-8)/t_j  (== argmax log(p+eps)+gumbel, exact
// monotone transform). Cross-multiplied compare; first index wins ties.
__device__ __forceinline__ float pool9(const float p[9], uint32_t k0, uint32_t k1,
                                       uint32_t base) {
  float bn = -1.0f, bd = 1.0f;   // best metric = bn/bd; any j beats this init
  int win = 0;
#pragma unroll
  for (int j = 0; j < 9; j++) {
    const float t = neglogu_at(k0, k1, base + (uint32_t)j);
    const float num = p[j] + 1e-8f;
    if (num * bd > bn * t) { bn = num; bd = t; win = j; }
  }
  return p[win];
}

// ---------------- W2 prep: [c2][c][kh][kw] -> [kk][o][c][t] ----------------
__global__ void w2p_kernel(const float *__restrict__ w2) {
  int idx = blockIdx.x * 256 + threadIdx.x;   // 49*24*96*8 = 903168 exact
  int t = idx & 7;
  int r = idx >> 3;
  int c = r % 96;
  int u = r / 96;
  int o = u % 24;
  int kk = u / 24;
  g_w2p8[idx] = w2[((o * 8 + t) * 96 + c) * 49 + kk];
}

// ---------------- Layer 1: dy-split, 4 ch/item, 600 threads (R11) ----------------
// grid (64, 6, 3): (batch, 16-ch group, 10-row decade). 2 items/thread.
__global__ void __launch_bounds__(600) l1_kernel(const float *__restrict__ x,
                                                 const float *__restrict__ w1,
                                                 const float *__restrict__ b1,
                                                 uint32_t k0, uint32_t k1) {
  extern __shared__ float sm[];
  float *xs = sm;                        // [3][36][96] = 10368 floats
  u64 *ws4 = (u64 *)(sm + 10368);        // [4 quads][147 taps][2 pairs]
  const int b = blockIdx.x, cg = blockIdx.y, d = blockIdx.z;
  const int cbase = cg * 16;

  for (int i = threadIdx.x; i < 3 * 36 * 96 / 4; i += 600) {
    int e = i * 4;
    int ci = e / (36 * 96);
    int r = e - ci * 36 * 96;
    ((float4 *)xs)[i] =
        *(const float4 *)(x + (size_t)b * 27648 + ci * 9216 + (30 * d) * 96 + r);
  }
  // ws4[(qo*147 + tap)*2 + s] = pack(w1[ch 4qo+2s], w1[ch 4qo+2s+1]).
  for (int i = threadIdx.x; i < 8 * 147; i += 600) {
    int pr = i / 147, m = i - pr * 147;   // pr = 2*qo + s
    int qo = pr >> 1, s = pr & 1;
    float a = w1[(cbase + qo * 4 + s * 2 + 0) * 147 + m];
    float bb = w1[(cbase + qo * 4 + s * 2 + 1) * 147 + m];
    ws4[(qo * 147 + m) * 2 + s] =
        (u64)__float_as_uint(a) | ((u64)__float_as_uint(bb) << 32);
  }
  __syncthreads();

  for (int item = threadIdx.x; item < 1200; item += 600) {
    const int qo = item / 300, pos = item - qo * 300;
    const int hl = pos / 30, wb = pos - hl * 30;
    const int r0 = hl * 3, q0 = wb * 3;
    const u64 *wq = ws4 + qo * 294;

    u64 acc0[9], acc1[9];
#pragma unroll
    for (int j = 0; j < 9; j++) { acc0[j] = 0ull; acc1[j] = 0ull; }

#pragma unroll
    for (int dy = 0; dy < 3; dy++) {
#pragma unroll 1
      for (int kh = 0; kh < 7; kh++) {
        // 27-float window: input row (r0+dy+kh) per ci, cols q0..q0+8.
        float v[3][9];
#pragma unroll
        for (int ci = 0; ci < 3; ci++) {
          const float *row = xs + (ci * 36 + r0 + dy + kh) * 96 + q0;
#pragma unroll
          for (int e = 0; e < 9; e++) v[ci][e] = row[e];
        }
        const u64 *wkh = wq + kh * 14;
#pragma unroll
        for (int kw = 0; kw < 7; kw++) {
#pragma unroll
          for (int ci = 0; ci < 3; ci++) {
            const ulonglong2 wv =
                *(const ulonglong2 *)(wkh + (ci * 49 + kw) * 2);
#pragma unroll
            for (int dx = 0; dx < 3; dx++) {
              const u64 vs = splat2(v[ci][kw + dx]);
              ffma2(acc0[dy * 3 + dx], vs, wv.x);
              ffma2(acc1[dy * 3 + dx], vs, wv.y);
            }
          }
        }
      }
    }

    const int hb = d * 10 + hl;
    const int posg = hb * 30 + wb;
#pragma unroll
    for (int k4 = 0; k4 < 4; k4++) {
      const int c = cbase + qo * 4 + k4;
      float accs[9];
#pragma unroll
      for (int j = 0; j < 9; j++) {
        u64 a = (k4 < 2) ? acc0[j] : acc1[j];
        accs[j] = (k4 & 1) ? lane1(a) : lane0(a);
      }
      const float bias = b1[c];
      float p[9];
#pragma unroll
      for (int j = 0; j < 9; j++) {
        float pre = (accs[j] + bias) / 0.04f;
        p[j] = 1.0f / (1.0f + expf(-pre));   // exact: emitted values unchanged
      }
      const uint32_t base = (((uint32_t)(b * 96 + c)) * 900u + (uint32_t)posg) * 9u;
      g_h1[((b * 30 + hb) * 30 + wb) * 96 + c] = pool9(p, k0, k1, base);
    }
  }
}

// ---------------- Layer 2: 8 ch/thread, pipelined weights (R8) ----------------
// grid (64, 8, 2): (batch, pooled row, wb-half). 96 threads = 24 octets x 4 wl.
__global__ void __launch_bounds__(96, 3) l2_kernel(const float *__restrict__ b2,
                                                   float *__restrict__ out,
                                                   uint32_t k0, uint32_t k1) {
  extern __shared__ float hs[];  // [9 rows][18 cols][CP]
  const int b = blockIdx.x, hb = blockIdx.y, sHalf = blockIdx.z;
  const int tid = threadIdx.x;

  for (int i = tid; i < 9 * 432; i += 96) {
    int row = i / 432, r = i - row * 432;
    int e = r * 4;
    int cl = e / 96, c = e - cl * 96;
    float4 dv = *(const float4 *)(g_h1 +
        ((size_t)(b * 30 + hb * 3 + row) * 30 + 12 * sHalf) * 96 + e);
    *(float4 *)&hs[(row * 18 + cl) * CP + c] = dv;
  }
  __syncthreads();

  const int o = tid >> 2;
  const int wl = tid & 3;
  const int wb = sHalf * 4 + wl;
  const int q0 = wl * 3;

  u64 acc[4][9];
#pragma unroll
  for (int i = 0; i < 4; i++)
#pragma unroll
    for (int j = 0; j < 9; j++) acc[i][j] = 0ull;

  const u64 *w8 = (const u64 *)g_w2p8;

  const u64 *wk = w8 + (size_t)o * 384;   // kk = 0
  ulonglong2 P[8];
  {
    const ulonglong2 *p0 = (const ulonglong2 *)wk;
#pragma unroll
    for (int t = 0; t < 8; t++) P[t] = p0[t];
  }

#pragma unroll 1
  for (int kh = 0; kh < 7; kh++) {
#pragma unroll 1
    for (int kw = 0; kw < 7; kw++) {
      const int kk = kh * 7 + kw;
      const float *hrow = hs + (kh * 18 + q0 + kw) * CP;
      const u64 *wk_next =
          w8 + ((size_t)((kk < 48) ? kk + 1 : kk) * 24 + o) * 384;
#pragma unroll 2
      for (int c4 = 0; c4 < 24; c4++) {
        ulonglong2 W[8];
#pragma unroll
        for (int t = 0; t < 8; t++) W[t] = P[t];
        const ulonglong2 *np = (const ulonglong2 *)(
            (c4 < 23) ? (wk + (c4 + 1) * 16) : wk_next);
#pragma unroll
        for (int t = 0; t < 8; t++) P[t] = np[t];

        // Per-acc chain order over (kh, kw, c4, cc) = (kh, kw, c) ascending.
#pragma unroll
        for (int j = 0; j < 9; j++) {
          const int dy = j / 3, dx = j - dy * 3;
          const float4 vv = *(const float4 *)(hrow + (dy * 18 + dx) * CP + c4 * 4);
#pragma unroll
          for (int cc = 0; cc < 4; cc++) {
            const u64 vs = splat2(((const float *)&vv)[cc]);
            ffma2(acc[0][j], vs, W[cc * 2].x);
            ffma2(acc[1][j], vs, W[cc * 2].y);
            ffma2(acc[2][j], vs, W[cc * 2 + 1].x);
            ffma2(acc[3][j], vs, W[cc * 2 + 1].y);
          }
        }
      }
      wk = wk_next;
    }
  }

#pragma unroll
  for (int i = 0; i < 4; i++) {
#pragma unroll
    for (int s = 0; s < 2; s++) {
      const int c2 = o * 8 + i * 2 + s;
      float accs[9];
#pragma unroll
      for (int j = 0; j < 9; j++)
        accs[j] = s ? lane1(acc[i][j]) : lane0(acc[i][j]);
      const float bias = b2[c2];
      float p[9];
#pragma unroll
      for (int j = 0; j < 9; j++) {
        float pre = (accs[j] + bias) / 0.04f;
        p[j] = 1.0f / (1.0f + expf(-pre));   // exact: emitted values unchanged
      }
      const uint32_t oidx =
          (((uint32_t)b * 192u + (uint32_t)c2) * 8u + (uint32_t)hb) * 8u + (uint32_t)wb;
      out[oidx] = pool9(p, k0, k1, oidx * 9u);
    }
  }
}

// ---------------- Launch ----------------
extern "C" void kernel_launch(void *const *d_in, const int *in_sizes, int n_in,
                              void *d_out, int out_size) {
  const float *x  = (const float *)d_in[0];
  const float *w1 = (const float *)d_in[1];
  const float *b1 = (const float *)d_in[2];
  const float *w2 = (const float *)d_in[3];
  const float *b2 = (const float *)d_in[4];

  uint32_t kp1_0, kp1_1, kp2_0, kp2_1;
  tf2x32(0u, 42u, 0u, 0u, kp1_0, kp1_1);
  tf2x32(0u, 42u, 0u, 1u, kp2_0, kp2_1);

  const int l1_smem = 10368 * 4 + 8 * 147 * 8;   // 50,880 B
  const int l2_smem = 9 * 18 * CP * 4;           // 64,800 B
  cudaFuncSetAttribute(l1_kernel, cudaFuncAttributeMaxDynamicSharedMemorySize, l1_smem);
  cudaFuncSetAttribute(l2_kernel, cudaFuncAttributeMaxDynamicSharedMemorySize, l2_smem);

  l1_kernel<<<dim3(64, 6, 3), 600, l1_smem>>>(x, w1, b1, kp1_0, kp1_1);
  w2p_kernel<<<49 * 24 * 96 * 8 / 256, 256>>>(w2);
  l2_kernel<<<dim3(64, 8, 2), 96, l2_smem>>>(b2, (float *)d_out, kp2_0, kp2_1);
}